// round 4
// baseline (speedup 1.0000x reference)
#include <cuda_runtime.h>
#include <math.h>
#include <stdint.h>

#define BATCH 1024
#define NV    6890
#define NJ    24
#define NB    10
#define NP    207
#define KP    224          // 10 betas + 207 pose_feature + 7 pad (v_template handled in skin)
#define KA    28           // KP / 8 k-atoms
#define NCOL  20670        // V*3
#define NPAD  20736        // padded N (162 * 128)
#define NBLK  162          // NPAD / 128
#define MBLK  8            // BATCH / 128
#define JCH   8            // v-chunks per joint for jreg
#define CHSZ  862          // ceil(NV/JCH)

// ---------------- scratch (device globals; no allocation allowed) ----------------
__device__ float g_Bfrag[NBLK * KA * 16 * 32 * 2];   // tf32 B fragments (18.6 MB)
__device__ float g_vposed[BATCH * NPAD];             // v_posed minus template (84.9 MB)
__device__ float g_AB[BATCH * KP];                   // per-batch GEMM A rows
__device__ float g_A[BATCH * NJ * 12];               // per-batch skinning transforms (3x4)
__device__ float g_root[BATCH * 3];                  // posed joint 0 (root)
__device__ float g_Jpart[NJ * JCH * 33];             // jreg partials

__constant__ int c_parents[NJ] = {-1,0,0,0,1,2,3,4,5,6,7,8,9,9,9,12,13,14,16,17,18,19,20,21};

// output section offsets (floats)
#define OFF_VERTS 0
#define OFF_J     (BATCH * NCOL)
#define OFF_R     (OFF_J + BATCH * NJ * 3)
#define OFF_F     (OFF_R + BATCH * NJ * 9)

// ---------------- helpers ----------------
__device__ __forceinline__ uint32_t tf32_bits(float x) {
    uint32_t u;
    asm("cvt.rna.tf32.f32 %0, %1;" : "=r"(u) : "f"(x));
    return u;
}
__device__ __forceinline__ void mma_tf32(float4& d, uint4 a, uint2 b) {
    asm volatile(
        "mma.sync.aligned.m16n8k8.row.col.f32.tf32.tf32.f32 "
        "{%0,%1,%2,%3}, {%4,%5,%6,%7}, {%8,%9}, {%0,%1,%2,%3};"
        : "+f"(d.x), "+f"(d.y), "+f"(d.z), "+f"(d.w)
        : "r"(a.x), "r"(a.y), "r"(a.z), "r"(a.w), "r"(b.x), "r"(b.y));
}
typedef unsigned long long u64;
__device__ __forceinline__ u64 pack2(float x, float y) {
    u64 r; asm("mov.b64 %0, {%1, %2};" : "=l"(r) : "f"(x), "f"(y)); return r;
}
__device__ __forceinline__ u64 ffma2(u64 a, u64 b, u64 c) {
    u64 d; asm("fma.rn.f32x2 %0, %1, %2, %3;" : "=l"(d) : "l"(a), "l"(b), "l"(c)); return d;
}
__device__ __forceinline__ float2 unpack2(u64 v) {
    float2 f; asm("mov.b64 {%0, %1}, %2;" : "=f"(f.x), "=f"(f.y) : "l"(v)); return f;
}

// ============================================================================
// Kernel 1 (fused front): blocks [0, NJ*JCH) = jreg partials;
//                         blocks [NJ*JCH, +NBLK*KA) = tf32 B-fragment build
// ============================================================================
#define JREG_BLOCKS (NJ * JCH)
__global__ void __launch_bounds__(256) k_front(const float* __restrict__ Jreg,
                                               const float* __restrict__ vtmpl,
                                               const float* __restrict__ shapedirs,
                                               const float* __restrict__ posedirs) {
    __shared__ float smem_f[8 * 128];
    int tid = threadIdx.x;

    if (blockIdx.x < JREG_BLOCKS) {
        // ---- jreg partial: joint j, chunk c ----
        int j = blockIdx.x >> 3;
        int c = blockIdx.x & 7;
        int vbeg = c * CHSZ;
        int vend = vbeg + CHSZ; if (vend > NV) vend = NV;
        float acc[33];
#pragma unroll
        for (int i = 0; i < 33; i++) acc[i] = 0.f;
        for (int v = vbeg + tid; v < vend; v += 256) {
            float r = Jreg[j * NV + v];
#pragma unroll
            for (int k = 0; k < 3; k++) {
                acc[k] = fmaf(r, vtmpl[v * 3 + k], acc[k]);
#pragma unroll
                for (int l = 0; l < NB; l++)
                    acc[3 + k * NB + l] = fmaf(r, shapedirs[(v * 3 + k) * NB + l], acc[3 + k * NB + l]);
            }
        }
        float (*part)[33] = (float (*)[33])smem_f;
        int lane = tid & 31, warp = tid >> 5;
#pragma unroll
        for (int i = 0; i < 33; i++) {
            float x = acc[i];
            for (int off = 16; off; off >>= 1) x += __shfl_down_sync(0xffffffffu, x, off);
            if (lane == 0) part[warp][i] = x;
        }
        __syncthreads();
        if (tid < 33) {
            float s = 0.f;
#pragma unroll
            for (int w = 0; w < 8; w++) s += part[w][tid];
            g_Jpart[blockIdx.x * 33 + tid] = s;
        }
    } else {
        // ---- B fragment build ----
        int blk = blockIdx.x - JREG_BLOCKS;
        int n_blk = blk % NBLK;
        int ka = blk / NBLK;
        float (*sW8)[128] = (float (*)[128])smem_f;
#pragma unroll
        for (int r = 0; r < 4; r++) {
            int e = tid + r * 256;
            int kk = e >> 7;
            int nn = e & 127;
            int k = ka * 8 + kk;
            int n = n_blk * 128 + nn;
            float val = 0.f;
            if (n < NCOL) {
                if (k < NB)            val = shapedirs[n * NB + k];
                else if (k < NB + NP)  val = posedirs[(k - NB) * NCOL + n];
            }
            sW8[kk][nn] = val;
        }
        __syncthreads();
        float2* gB = (float2*)g_Bfrag;
#pragma unroll
        for (int r = 0; r < 2; r++) {
            int e = tid + r * 256;
            int n_sub = e >> 5;
            int t = e & 31;
            int g = t >> 2, tig = t & 3;
            float b0 = sW8[tig][n_sub * 8 + g];
            float b1 = sW8[tig + 4][n_sub * 8 + g];
            float2 v;
            v.x = __uint_as_float(tf32_bits(b0));
            v.y = __uint_as_float(tf32_bits(b1));
            gB[((size_t)(n_blk * KA + ka) * 16 + n_sub) * 32 + t] = v;
        }
    }
}

// ============================================================================
// Kernel 2: per-batch rodrigues / chain / A matrices / outputs J & R.
// 8 batches per block (one warp each); jreg partial reduce inlined.
// ============================================================================
__global__ void __launch_bounds__(256) k_mid(const float* __restrict__ pose,
                                             const float* __restrict__ betas,
                                             const float* __restrict__ gorient,
                                             float* __restrict__ out) {
    __shared__ float sJt[72];
    __shared__ float sJsd[720];
    __shared__ float sR[8][NJ][9];
    __shared__ float sJb[8][NJ][3];
    __shared__ float sG[8][NJ][12];
    int tid = threadIdx.x;

    // reduce jreg partials (same for all batches)
    for (int i = tid; i < 792; i += 256) {
        float s = 0.f;
        if (i < 72) {
            int j = i / 3, k = i % 3;
#pragma unroll
            for (int c = 0; c < JCH; c++) s += g_Jpart[(j * JCH + c) * 33 + k];
            sJt[i] = s;
        } else {
            int i2 = i - 72;
            int j = i2 / 30, l = i2 % 30;
#pragma unroll
            for (int c = 0; c < JCH; c++) s += g_Jpart[(j * JCH + c) * 33 + 3 + l];
            sJsd[i2] = s;
        }
    }
    __syncthreads();

    int g = tid >> 5;          // batch group 0..7
    int t = tid & 31;
    int b = blockIdx.x * 8 + g;

    if (t < NJ) {
        float rx, ry, rz;
        if (t == 0) { rx = gorient[b*3+0]; ry = gorient[b*3+1]; rz = gorient[b*3+2]; }
        else { const float* p = pose + b*69 + (t-1)*3; rx = p[0]; ry = p[1]; rz = p[2]; }
        float xa = rx + 1e-8f, ya = ry + 1e-8f, za = rz + 1e-8f;
        float angle = sqrtf(xa*xa + ya*ya + za*za);
        float inv = 1.f / angle;
        float ax = rx*inv, ay = ry*inv, az = rz*inv;
        float s = sinf(angle), c = cosf(angle);
        float K[9] = {0.f,-az,ay, az,0.f,-ax, -ay,ax,0.f};
        float R[9];
#pragma unroll
        for (int r = 0; r < 3; r++)
#pragma unroll
            for (int cc = 0; cc < 3; cc++) {
                float k2 = 0.f;
#pragma unroll
                for (int m = 0; m < 3; m++) k2 += K[r*3+m] * K[m*3+cc];
                R[r*3+cc] = (r==cc ? 1.f : 0.f) + s*K[r*3+cc] + (1.f - c)*k2;
            }
#pragma unroll
        for (int i = 0; i < 9; i++) sR[g][t][i] = R[i];
#pragma unroll
        for (int i = 0; i < 9; i++) out[OFF_R + (size_t)b*216 + t*9 + i] = R[i];
        if (t >= 1) {
#pragma unroll
            for (int i = 0; i < 9; i++) {
                float id = (i==0 || i==4 || i==8) ? 1.f : 0.f;
                g_AB[b*KP + NB + (t-1)*9 + i] = R[i] - id;
            }
        }
#pragma unroll
        for (int k = 0; k < 3; k++) {
            float jr = sJt[t*3 + k];
#pragma unroll
            for (int l = 0; l < NB; l++)
                jr = fmaf(betas[b*NB + l], sJsd[t*30 + k*NB + l], jr);
            sJb[g][t][k] = jr;
        }
    }
    if (t < NB) g_AB[b*KP + t] = betas[b*NB + t];
    if (t == 24) {
#pragma unroll
        for (int i = NB + NP; i < KP; i++) g_AB[b*KP + i] = 0.f;
    }
    __syncwarp();

    if (t == 0) {
#pragma unroll
        for (int r = 0; r < 3; r++) {
            sG[g][0][r*4+0] = sR[g][0][r*3+0];
            sG[g][0][r*4+1] = sR[g][0][r*3+1];
            sG[g][0][r*4+2] = sR[g][0][r*3+2];
            sG[g][0][r*4+3] = sJb[g][0][r];
        }
        for (int j = 1; j < NJ; j++) {
            int p = c_parents[j];
            float rel0 = sJb[g][j][0] - sJb[g][p][0];
            float rel1 = sJb[g][j][1] - sJb[g][p][1];
            float rel2 = sJb[g][j][2] - sJb[g][p][2];
#pragma unroll
            for (int r = 0; r < 3; r++) {
                float g0 = sG[g][p][r*4+0], g1 = sG[g][p][r*4+1], g2 = sG[g][p][r*4+2];
#pragma unroll
                for (int cc = 0; cc < 3; cc++)
                    sG[g][j][r*4+cc] = g0*sR[g][j][0*3+cc] + g1*sR[g][j][1*3+cc] + g2*sR[g][j][2*3+cc];
                sG[g][j][r*4+3] = g0*rel0 + g1*rel1 + g2*rel2 + sG[g][p][r*4+3];
            }
        }
        g_root[b*3+0] = sG[g][0][3];
        g_root[b*3+1] = sG[g][0][7];
        g_root[b*3+2] = sG[g][0][11];
    }
    __syncwarp();

    if (t < NJ) {
        float j0 = sJb[g][t][0], j1 = sJb[g][t][1], j2 = sJb[g][t][2];
#pragma unroll
        for (int r = 0; r < 3; r++) {
            float g0 = sG[g][t][r*4+0], g1 = sG[g][t][r*4+1], g2 = sG[g][t][r*4+2], gt = sG[g][t][r*4+3];
            float* A = &g_A[((size_t)b*NJ + t)*12 + r*4];
            A[0] = g0; A[1] = g1; A[2] = g2;
            A[3] = gt - (g0*j0 + g1*j1 + g2*j2);
            out[OFF_J + (size_t)b*72 + t*3 + r] = gt - sG[g][0][r*4+3];
        }
    }
}

// ============================================================================
// Kernel 3: tf32 tensor-core GEMM.  Block 128x128, 8 warps (4m x 2n).
// B fragments pre-packed; A staged fp32 from g_AB (padded smem, cvt in regs).
// ============================================================================
__global__ void __launch_bounds__(256, 2) k_gemm() {
    __shared__ float sAf[2][128][9];   // padded: conflict-free fragment reads
    __shared__ uint2 sB[2][16][32];
    int n_blk = blockIdx.x;
    int m_blk = blockIdx.y;
    int tid = threadIdx.x;
    int lane = tid & 31;
    int wid = tid >> 5;
    int wm = wid >> 1;                 // 0..3
    int wn = wid & 1;                  // 0..1
    int g = lane >> 2, tig = lane & 3;

    const uint2* gB = (const uint2*)g_Bfrag + (size_t)n_blk * KA * 512;
    int bm = m_blk * 128;
    int arow = tid >> 1;
    int acol = (tid & 1) * 4;

    float4 acc[2][8];
#pragma unroll
    for (int i = 0; i < 2; i++)
#pragma unroll
        for (int j = 0; j < 8; j++) acc[i][j] = make_float4(0.f, 0.f, 0.f, 0.f);

    // prefetch ka=0
    float4 pa = *(const float4*)&g_AB[(bm + arow) * KP + acol];
    uint2 pb0 = gB[tid];
    uint2 pb1 = gB[tid + 256];

    int b_ns0 = tid >> 5;
    int b_ns1 = 8 + (tid >> 5);

    for (int ka = 0; ka < KA; ka++) {
        int buf = ka & 1;
        sAf[buf][arow][acol+0] = pa.x;
        sAf[buf][arow][acol+1] = pa.y;
        sAf[buf][arow][acol+2] = pa.z;
        sAf[buf][arow][acol+3] = pa.w;
        sB[buf][b_ns0][lane] = pb0;
        sB[buf][b_ns1][lane] = pb1;
        __syncthreads();
        if (ka + 1 < KA) {
            pa  = *(const float4*)&g_AB[(bm + arow) * KP + (ka + 1) * 8 + acol];
            pb0 = gB[(ka + 1) * 512 + tid];
            pb1 = gB[(ka + 1) * 512 + tid + 256];
        }
        uint4 af[2];
#pragma unroll
        for (int i = 0; i < 2; i++) {
            int r0 = wm * 32 + i * 16 + g;
            af[i].x = tf32_bits(sAf[buf][r0][tig]);
            af[i].y = tf32_bits(sAf[buf][r0 + 8][tig]);
            af[i].z = tf32_bits(sAf[buf][r0][tig + 4]);
            af[i].w = tf32_bits(sAf[buf][r0 + 8][tig + 4]);
        }
        uint2 bf[8];
#pragma unroll
        for (int j = 0; j < 8; j++) bf[j] = sB[buf][wn * 8 + j][lane];
#pragma unroll
        for (int i = 0; i < 2; i++)
#pragma unroll
            for (int j = 0; j < 8; j++)
                mma_tf32(acc[i][j], af[i], bf[j]);
    }

    // epilogue
#pragma unroll
    for (int i = 0; i < 2; i++) {
        int r0 = m_blk * 128 + (wm * 2 + i) * 16 + g;
#pragma unroll
        for (int j = 0; j < 8; j++) {
            int c = n_blk * 128 + (wn * 8 + j) * 8 + tig * 2;
            *(float2*)&g_vposed[(size_t)r0 * NPAD + c] = make_float2(acc[i][j].x, acc[i][j].y);
            *(float2*)&g_vposed[(size_t)(r0 + 8) * NPAD + c] = make_float2(acc[i][j].z, acc[i][j].w);
        }
    }
}

// ============================================================================
// Kernel 4: skinning (+ v_template add, fp32 exact), f32x2 accumulation.
// ============================================================================
#define SK_MB 8
#define SK_VT 128
__global__ void __launch_bounds__(256) k_skin(const float* __restrict__ wgt,
                                              const float* __restrict__ vtmpl,
                                              float* __restrict__ out_verts) {
    __shared__ __align__(16) float sW[SK_VT][25];
    __shared__ __align__(16) float sA[SK_MB][NJ][12];
    __shared__ float sRoot[SK_MB][3];
    __shared__ float sVT[SK_VT * 3];
    int v0 = blockIdx.x * SK_VT;
    int b0 = blockIdx.y * SK_MB;
    int tid = threadIdx.x;

    for (int i = tid; i < SK_VT * NJ; i += 256) {
        int vv = i / NJ, jj = i % NJ;
        int v = v0 + vv;
        sW[vv][jj] = (v < NV) ? wgt[v * NJ + jj] : 0.f;
    }
    for (int i = tid; i < SK_MB * NJ * 12; i += 256)
        ((float*)sA)[i] = g_A[(size_t)b0 * NJ * 12 + i];
    for (int i = tid; i < SK_VT * 3; i += 256) {
        int idx = v0 * 3 + i;
        sVT[i] = (idx < NCOL) ? vtmpl[idx] : 0.f;
    }
    if (tid < SK_MB * 3)
        sRoot[tid / 3][tid % 3] = g_root[(b0 + tid / 3) * 3 + tid % 3];
    __syncthreads();

    int lane = tid & 31;
    int bi = tid >> 5;
    int b = b0 + bi;

    u64 T2[4][6];
#pragma unroll
    for (int i = 0; i < 4; i++)
#pragma unroll
        for (int r = 0; r < 6; r++) T2[i][r] = 0ull;

#pragma unroll
    for (int j = 0; j < NJ; j++) {
        const u64* a2 = (const u64*)&sA[bi][j][0];
        u64 av[6];
#pragma unroll
        for (int r = 0; r < 6; r++) av[r] = a2[r];
#pragma unroll
        for (int i = 0; i < 4; i++) {
            float w = sW[lane + 32*i][j];
            u64 w2 = pack2(w, w);
#pragma unroll
            for (int r = 0; r < 6; r++) T2[i][r] = ffma2(w2, av[r], T2[i][r]);
        }
    }

    const float* vp = g_vposed + (size_t)b * NPAD;
    float rx = sRoot[bi][0], ry = sRoot[bi][1], rz = sRoot[bi][2];
#pragma unroll
    for (int i = 0; i < 4; i++) {
        int v = v0 + lane + 32*i;
        if (v < NV) {
            float T[12];
#pragma unroll
            for (int r = 0; r < 6; r++) {
                float2 f = unpack2(T2[i][r]);
                T[2*r] = f.x; T[2*r+1] = f.y;
            }
            int vv = lane + 32*i;
            float px = vp[v*3+0] + sVT[vv*3+0];
            float py = vp[v*3+1] + sVT[vv*3+1];
            float pz = vp[v*3+2] + sVT[vv*3+2];
            float ox = T[0]*px + T[1]*py + T[2]*pz  + T[3]  - rx;
            float oy = T[4]*px + T[5]*py + T[6]*pz  + T[7]  - ry;
            float oz = T[8]*px + T[9]*py + T[10]*pz + T[11] - rz;
            size_t o = (size_t)b * NCOL + (size_t)v * 3;
            out_verts[o+0] = ox; out_verts[o+1] = oy; out_verts[o+2] = oz;
        }
    }
}

// ============================================================================
// Kernel 5: jfv = (Jh @ verts_out), s[j]-s[0].  2 batches / block, f32x2 packed.
// ============================================================================
__global__ void __launch_bounds__(256) k_jfv(const float* __restrict__ verts,
                                             const float* __restrict__ Jh,
                                             float* __restrict__ out_jfv) {
    int b0 = blockIdx.x * 2;
    int tid = threadIdx.x;
    u64 acc2[51];
#pragma unroll
    for (int i = 0; i < 51; i++) acc2[i] = 0ull;

    const float* va_base = verts + (size_t)b0 * NCOL;
    const float* vb_base = va_base + NCOL;
    for (int v = tid; v < NV; v += 256) {
        const float* va = va_base + (size_t)v * 3;
        const float* vb = vb_base + (size_t)v * 3;
        u64 x2 = pack2(va[0], vb[0]);
        u64 y2 = pack2(va[1], vb[1]);
        u64 z2 = pack2(va[2], vb[2]);
#pragma unroll
        for (int j = 0; j < 17; j++) {
            float jr = Jh[j * NV + v];
            u64 jr2 = pack2(jr, jr);
            acc2[j*3+0] = ffma2(jr2, x2, acc2[j*3+0]);
            acc2[j*3+1] = ffma2(jr2, y2, acc2[j*3+1]);
            acc2[j*3+2] = ffma2(jr2, z2, acc2[j*3+2]);
        }
    }

    float a[102];
#pragma unroll
    for (int i = 0; i < 51; i++) {
        float2 f = unpack2(acc2[i]);
        a[i] = f.x;
        a[51 + i] = f.y;
    }

    __shared__ float red[8][102];
    int lane = tid & 31, warp = tid >> 5;
#pragma unroll
    for (int i = 0; i < 102; i++) {
        float x = a[i];
        for (int off = 16; off; off >>= 1) x += __shfl_down_sync(0xffffffffu, x, off);
        if (lane == 0) red[warp][i] = x;
    }
    __syncthreads();
    if (tid < 102) {
        float s = 0.f;
#pragma unroll
        for (int w = 0; w < 8; w++) s += red[w][tid];
        red[0][tid] = s;
    }
    __syncthreads();
    if (tid < 102) {
        int bb = tid / 51;
        int jk = tid % 51;
        int k = jk % 3;
        float val = red[0][tid] - red[0][bb * 51 + k];
        out_jfv[(size_t)(b0 + bb) * 51 + jk] = val;
    }
}

// ============================================================================
extern "C" void kernel_launch(void* const* d_in, const int* in_sizes, int n_in,
                              void* d_out, int out_size) {
    const float* pose      = (const float*)d_in[0];
    const float* betas     = (const float*)d_in[1];
    const float* gorient   = (const float*)d_in[2];
    const float* vtmpl     = (const float*)d_in[3];
    const float* shapedirs = (const float*)d_in[4];
    const float* posedirs  = (const float*)d_in[5];
    const float* Jreg      = (const float*)d_in[6];
    const float* Jh        = (const float*)d_in[7];
    const float* wgt       = (const float*)d_in[8];
    float* out = (float*)d_out;

    k_front<<<JREG_BLOCKS + NBLK * KA, 256>>>(Jreg, vtmpl, shapedirs, posedirs);
    k_mid<<<BATCH / 8, 256>>>(pose, betas, gorient, out);
    k_gemm<<<dim3(NBLK, MBLK), 256>>>();
    k_skin<<<dim3((NV + SK_VT - 1) / SK_VT, BATCH / SK_MB), 256>>>(wgt, vtmpl, out + OFF_VERTS);
    k_jfv<<<BATCH / 2, 256>>>(out + OFF_VERTS, Jh, out + OFF_F);
}